// round 16
// baseline (speedup 1.0000x reference)
#include <cuda_runtime.h>
#include <cuda_fp16.h>
#include <math.h>

#define BRAYS 4096
#define NSAMP 447
#define N3 (64*64*64)
#define M3 (128*128*128)
#define STEPV 0.015625f

typedef unsigned long long u64;
typedef unsigned int u32;

__device__ __forceinline__ void fma2(u64& d, u64 a, u64 b) {
    asm("fma.rn.f32x2 %0, %1, %2, %0;" : "+l"(d) : "l"(a), "l"(b));
}
__device__ __forceinline__ u64 pack2(float lo, float hi) {
    u64 r;
    asm("mov.b64 %0, {%1, %2};" : "=l"(r) : "f"(lo), "f"(hi));
    return r;
}
__device__ __forceinline__ float2 unpack2(u64 v) {
    float2 r;
    asm("mov.b64 {%0, %1}, %2;" : "=f"(r.x), "=f"(r.y) : "l"(v));
    return r;
}
__device__ __forceinline__ void mma16(float* c, const u32* a, u32 b0, u32 b1) {
    asm volatile(
        "mma.sync.aligned.m16n8k16.row.col.f32.f16.f16.f32 "
        "{%0,%1,%2,%3},{%4,%5,%6,%7},{%8,%9},{%0,%1,%2,%3};"
        : "+f"(c[0]), "+f"(c[1]), "+f"(c[2]), "+f"(c[3])
        : "r"(a[0]), "r"(a[1]), "r"(a[2]), "r"(a[3]), "r"(b0), "r"(b1));
}
__device__ __forceinline__ u32 packh2(__half a, __half b) {
    __half2 h = __halves2half2(a, b);
    return *(u32*)&h;
}
__device__ __forceinline__ u64 cvpack(float a, float b) {
    __half ha = __float2half_rn(a), hb = __float2half_rn(b);
    __half la = __float2half_rn(a - __half2float(ha));
    __half lb = __float2half_rn(b - __half2float(hb));
    return (u64)packh2(ha, hb) | ((u64)packh2(la, lb) << 32);
}
__device__ __forceinline__ u32 smaddr(const void* p) {
    u32 a;
    asm("{ .reg .u64 t; cvta.to.shared.u64 t, %1; cvt.u32.u64 %0, t; }"
        : "=r"(a) : "l"(p));
    return a;
}
__device__ __forceinline__ void cp_async8(u32 dst, const void* src, int src_sz) {
    asm volatile("cp.async.ca.shared.global [%0], [%1], 8, %2;"
                 :: "r"(dst), "l"(src), "r"(src_sz) : "memory");
}
__device__ __forceinline__ void cp_async16(u32 dst, const void* src) {
    asm volatile("cp.async.cg.shared.global [%0], [%1], 16;"
                 :: "r"(dst), "l"(src) : "memory");
}
#define CP_COMMIT() asm volatile("cp.async.commit_group;" ::: "memory")
#define CP_WAIT(n)  asm volatile("cp.async.wait_group %0;" :: "n"(n) : "memory")

__host__ __device__ __forceinline__ int cp_to_ci(int cp, int half) {
    if (cp < 6)  return cp * 2 + half;
    if (cp < 38) { int q = cp - 6;  return 12 + (q >> 3) * 16 + half * 8 + (q & 7); }
    {            int q = cp - 38; return 76 + (q >> 3) * 16 + half * 8 + (q & 7); }
}

// ---------------- scratch -----------------------------------------------------
// AoS slot order: slot 2g = channel g, slot 2g+1 = channel g+8 (g<8);
// slots 16..18 = sobel grads; slot 19 pad.
__device__ float g_dens[M3];
__device__ __align__(16) float g_va[M3 * 20];
__device__ float g_sdfs[BRAYS * NSAMP];
__device__ float g_rgbs[BRAYS * NSAMP * 3];
__device__ __align__(16) u64 g_cv[70 * N3];          // also sobel scratch

#define WCH_H 15552
__device__ __align__(16) u32 g_w1p[2 * WCH_H];
__device__ __align__(16) u32 g_w2p[10 * WCH_H];
#define W3_TOTAL (18*27*2*4*24)
__device__ __align__(16) u32 g_w3p[W3_TOTAL];

// ---- fused prep: weight split + grid convert + rgbs zero ---------------------
#define PREP_W_TOTAL (12 * WCH_H + W3_TOTAL)
#define PREP_CV_TOTAL (6 * N3)
#define PREP_RGB_TOTAL (BRAYS * NSAMP * 3)
#define PREP_TOTAL (PREP_W_TOTAL + PREP_CV_TOTAL + PREP_RGB_TOTAL)
__global__ void prep_all(const float* __restrict__ w1,
                         const float* __restrict__ w2,
                         const float* __restrict__ w3,
                         const float* __restrict__ grid)
{
    int i = blockIdx.x * 256 + threadIdx.x;
    if (i < 12 * WCH_H) {
        const float* w; u32* dst; int CIN; int idx; int conv2;
        if (i < 2 * WCH_H) { w = w1; dst = g_w1p; CIN = 12; idx = i; conv2 = 0; }
        else { w = w2; dst = g_w2p; CIN = 76; idx = i - 2 * WCH_H; conv2 = 1; }
        int ch = idx / WCH_H, r = idx % WCH_H;
        int tap = r / 576, r2 = r % 576;
        int plane = r2 / 288, r3 = r2 % 288;
        int cpl = r3 / 72, co = r3 % 72;
        int cp = ch * 4 + cpl;
        int ci0, ci1;
        if (conv2) { ci0 = (cp < 38) ? cp_to_ci(cp, 0) : 999;
                     ci1 = (cp < 38) ? cp_to_ci(cp, 1) : 999; }
        else       { ci0 = 2 * cp; ci1 = 2 * cp + 1; }
        float v0 = (co < 64 && ci0 < CIN) ? __ldg(&w[co * (CIN * 27) + ci0 * 27 + tap]) : 0.f;
        float v1 = (co < 64 && ci1 < CIN) ? __ldg(&w[co * (CIN * 27) + ci1 * 27 + tap]) : 0.f;
        __half h0 = __float2half_rn(v0);
        __half l0 = __float2half_rn(v0 - __half2float(h0));
        __half h1 = __float2half_rn(v1);
        __half l1 = __float2half_rn(v1 - __half2float(h1));
        dst[idx] = plane ? packh2(l0, l1) : packh2(h0, h1);
        return;
    }
    if (i < PREP_W_TOTAL) {
        int idx = i - 12 * WCH_H;
        int co = idx % 24; int t = idx / 24;
        int cpl = t % 4; t /= 4;
        int plane = t % 2; t /= 2;
        int tap = t % 27; int ch = t / 27;
        int kz = tap / 9, ky = (tap / 3) % 3, kx = tap % 3;
        int cp = ch * 4 + cpl;
        float v0 = 0.f, v1 = 0.f;
        if (co < 16 && cp < 70) {
            int ci0 = cp_to_ci(cp, 0), ci1 = cp_to_ci(cp, 1);
            int foff = co * 27 + (2 - kz) * 9 + (2 - ky) * 3 + (2 - kx);
            v0 = __ldg(&w3[ci0 * (16 * 27) + foff]);
            v1 = __ldg(&w3[ci1 * (16 * 27) + foff]);
        }
        __half h0 = __float2half_rn(v0);
        __half l0 = __float2half_rn(v0 - __half2float(h0));
        __half h1 = __float2half_rn(v1);
        __half l1 = __float2half_rn(v1 - __half2float(h1));
        g_w3p[idx] = plane ? packh2(l0, l1) : packh2(h0, h1);
        return;
    }
    if (i < PREP_W_TOTAL + PREP_CV_TOTAL) {
        int idx = i - PREP_W_TOTAL;
        int cp = idx / N3, v = idx - cp * N3;
        float v0 = __ldg(&grid[(2 * cp) * N3 + v]);
        float v1 = __ldg(&grid[(2 * cp + 1) * N3 + v]);
        g_cv[cp * N3 + v] = cvpack(v0, v1);
        return;
    }
    int idx = i - PREP_W_TOTAL - PREP_CV_TOTAL;
    if (idx < PREP_RGB_TOTAL) g_rgbs[idx] = 0.f;
}

// ======== pipelined tensor-core 3x3x3 conv + BN + ReLU (8x8x4 tile) =========
#define CIN_PAD4 724
#define CONV_SMEM_P (8*CIN_PAD4*8 + 2*WCH_H*4)   // 170752 B
template<int NCP, int NCH, int CPBASE>
__global__ void __launch_bounds__(512) conv_tc_kernel(
    const float* __restrict__ cb,
    const float* __restrict__ bg, const float* __restrict__ bb,
    const float* __restrict__ bm, const float* __restrict__ bv)
{
    extern __shared__ u64 smem64[];
    u64* s_in0 = smem64;
    u64* s_in1 = smem64 + 4 * CIN_PAD4;
    u32* s_w0  = (u32*)(smem64 + 8 * CIN_PAD4);
    u32* s_w1  = s_w0 + WCH_H;
    __shared__ float s_a[64], s_c[64];
    const u32* wp = (CPBASE == 6) ? g_w1p : g_w2p;

    const int tid = threadIdx.x;
    const int x0 = blockIdx.x * 8, y0 = blockIdx.y * 8, z0 = blockIdx.z * 4;
    if (tid < 64) {
        float s = bg[tid] * rsqrtf(bv[tid] + 1e-5f);
        s_a[tid] = s;
        s_c[tid] = cb[tid] * s + bb[tid] - bm[tid] * s;
    }
    const int warp = tid >> 5, lane = tid & 31;
    const int g = lane >> 2, tg = lane & 3;
    const int coh = (warp & 1) * 32;
    const int q4  = (warp >> 1) * 4;

    float acc[2][4][4];
#pragma unroll
    for (int m = 0; m < 2; m++)
#pragma unroll
        for (int j = 0; j < 4; j++)
#pragma unroll
            for (int c = 0; c < 4; c++) acc[m][j][c] = 0.f;

    auto stage = [&](int ch, int buf) {
        u64* dst_in = buf ? s_in1 : s_in0;
        u32* dst_w  = buf ? s_w1 : s_w0;
        for (int i = tid; i < 4 * 720; i += 512) {
            int cpl = i / 720, rem = i - cpl * 720;
            int z = rem / 120, rem2 = rem - z * 120;
            int y = rem2 / 12, x = rem2 - y * 12;
            int gx = x0 - 1 + x, gy = y0 - 1 + y, gz = z0 - 1 + z;
            int cp = ch * 4 + cpl;
            bool ok = (x < 10) && cp < NCP && (unsigned)gx < 64u
                      && (unsigned)gy < 64u && (unsigned)gz < 64u;
            const u64* src = ok ? &g_cv[cp * N3 + (gz * 64 + gy) * 64 + gx] : &g_cv[0];
            cp_async8(smaddr(&dst_in[cpl * CIN_PAD4 + z * 120 + y * 12 + x]),
                      src, ok ? 8 : 0);
        }
        const float4* ws4 = (const float4*)(wp + ch * WCH_H);
        float4* wd4 = (float4*)dst_w;
        for (int i = tid; i < WCH_H / 4; i += 512)
            cp_async16(smaddr(&wd4[i]), &ws4[i]);
    };

    stage(0, 0);
    CP_COMMIT();
    for (int ch = 0; ch < NCH; ch++) {
        int buf = ch & 1;
        if (ch + 1 < NCH) {
            stage(ch + 1, buf ^ 1);
            CP_COMMIT();
            CP_WAIT(1);
        } else {
            CP_WAIT(0);
        }
        __syncthreads();
        const u64* in_b = buf ? s_in1 : s_in0;
        const u32* w_b  = buf ? s_w1 : s_w0;
#pragma unroll 1
        for (int tap = 0; tap < 27; tap++) {
            int kz = tap / 9, ky = (tap / 3) % 3, kx = tap % 3;
            const u32* wb = w_b + tap * 576;
            u32 a[2][4];
#pragma unroll
            for (int mg = 0; mg < 2; mg++) {
                int c0g = coh + 16 * mg + g;
                a[mg][0] = wb[tg * 72 + c0g];
                a[mg][1] = wb[tg * 72 + c0g + 8];
                a[mg][2] = wb[(4 + tg) * 72 + c0g];
                a[mg][3] = wb[(4 + tg) * 72 + c0g + 8];
            }
#pragma unroll
            for (int j = 0; j < 4; j++) {
                int nt = q4 + j;
                int yy = nt & 7, zz = nt >> 3;
                int ro = ((zz + kz) * 10 + yy + ky) * 12 + g + kx;
                u64 b = in_b[tg * CIN_PAD4 + ro];
                u32 b0 = (u32)b, b1 = (u32)(b >> 32);
                mma16(acc[0][j], a[0], b0, b1);
                mma16(acc[1][j], a[1], b0, b1);
                mma16(acc[0][j], a[0], b1, b0);
                mma16(acc[1][j], a[1], b1, b0);
            }
        }
        __syncthreads();
    }
#pragma unroll
    for (int mg = 0; mg < 2; mg++) {
        int c0 = coh + 16 * mg;
        int coA = c0 + g, coB = c0 + g + 8;
        float aA = s_a[coA], cA = s_c[coA];
        float aB = s_a[coB], cB = s_c[coB];
        int cp = CPBASE + (c0 >> 4) * 8 + g;
#pragma unroll
        for (int j = 0; j < 4; j++) {
            int nt = q4 + j;
            int y = nt & 7, z = nt >> 3;
            int vb = ((z0 + z) * 64 + (y0 + y)) * 64 + x0 + 2 * tg;
            float* c = acc[mg][j];
            float vA0 = fmaxf(c[0] * aA + cA, 0.f);
            float vA1 = fmaxf(c[1] * aA + cA, 0.f);
            float vB0 = fmaxf(c[2] * aB + cB, 0.f);
            float vB1 = fmaxf(c[3] * aB + cB, 0.f);
            g_cv[cp * N3 + vb]     = cvpack(vA0, vB0);
            g_cv[cp * N3 + vb + 1] = cvpack(vA1, vB1);
        }
    }
}

// ======== pipelined tensor-core transposed conv (2 x-parity classes) ========
// Row-based staging (low ALU); epilogue float2 stores into pair-interleaved AoS.
#define DC_PAD 980
#define DC_SMEM (2*4*DC_PAD*8 + 2*12*192*4)   // 81152 B
__global__ void __launch_bounds__(256) deconv_tc_kernel(const float* __restrict__ cb)
{
    extern __shared__ u64 dsm[];
    u64* s_in0 = dsm;
    u64* s_in1 = dsm + 4 * DC_PAD;
    u32* s_wa  = (u32*)(dsm + 8 * DC_PAD);
    u32* s_wb  = s_wa + 12 * 192;
    __shared__ float s_bias[16];
    const int tid = threadIdx.x;
    const int qx0 = blockIdx.x * 8, qy0 = blockIdx.y * 8;
    const int qz0 = (blockIdx.z & 7) * 8;
    const int pyz = blockIdx.z >> 3;
    const int py = pyz & 1, pz = pyz >> 1;
    if (tid < 16) s_bias[tid] = __ldg(&cb[tid]);

    const int nyl = 1 + py, nzl = 1 + pz;
    const int ntapw = 3 * nyl * nzl;
    const bool x8ok = (qx0 < 56);

    const int warp = tid >> 5, lane = tid & 31;
    const int g = lane >> 2, tg = lane & 3;

    // row decomposition of staging: 324 rows = 4cp x 9z x 9y, 9 u64 each
    const int row0 = tid;                   // rows tid and tid+256 (if < 324)
    float acc[2][8][4];
#pragma unroll
    for (int m = 0; m < 2; m++)
#pragma unroll
        for (int j = 0; j < 8; j++)
#pragma unroll
            for (int c = 0; c < 4; c++) acc[m][j][c] = 0.f;

    auto stage = [&](int ch, int buf) {
        u64* dst_in = buf ? s_in1 : s_in0;
        u32* dst_w  = buf ? s_wb : s_wa;
#pragma unroll
        for (int rr = 0; rr < 2; rr++) {
            int r = row0 + rr * 256;
            if (r < 324) {
                int cpl = r / 81, rem = r - cpl * 81;
                int z = rem / 9, y = rem - z * 9;
                int gy = qy0 + y, gz = qz0 + z;
                int cp = ch * 4 + cpl;
                bool rowOk = (gy < 64) && (gz < 64) && (cp < 70);
                const u64* src = rowOk ? &g_cv[cp * N3 + (gz * 64 + gy) * 64 + qx0]
                                       : &g_cv[0];
                u32 d = smaddr(&dst_in[cpl * DC_PAD + (z * 9 + y) * 12]);
                int szr = rowOk ? 8 : 0;
#pragma unroll
                for (int x = 0; x < 8; x++)
                    cp_async8(d + 8 * x, src + (rowOk ? x : 0), szr);
                cp_async8(d + 64, src + (rowOk ? 8 : 0), (rowOk && x8ok) ? 8 : 0);
            }
        }
        for (int i = tid; i < ntapw * 48; i += 256) {
            int t = i / 48, r4 = i - t * 48;
            int kxi = t % 3, q = t / 3;
            int tyi = q % nyl, tzi = q / nyl;
            int ky = py ? tyi * 2 : 1;
            int kz = pz ? tzi * 2 : 1;
            const float4* src = (const float4*)(g_w3p + (ch * 27 + kz * 9 + ky * 3 + kxi) * 192);
            cp_async16(smaddr((float4*)dst_w + t * 48 + r4), src + r4);
        }
    };

    stage(0, 0);
    CP_COMMIT();
    for (int ch = 0; ch < 18; ch++) {
        int buf = ch & 1;
        if (ch + 1 < 18) {
            stage(ch + 1, buf ^ 1);
            CP_COMMIT();
            CP_WAIT(1);
        } else {
            CP_WAIT(0);
        }
        __syncthreads();
        const u64* in_b = buf ? s_in1 : s_in0;
        const u32* s_w  = buf ? s_wb : s_wa;
        for (int tzi = 0; tzi < nzl; tzi++)
        for (int tyi = 0; tyi < nyl; tyi++) {
            int t3 = (tzi * nyl + tyi) * 3;
            u32 a0[4], a1[4], a2[4];
            {
                const u32* w0 = s_w + t3 * 192;
                const u32* w1 = w0 + 192;
                const u32* w2 = w1 + 192;
                int o1 = tg * 24 + g, o2 = o1 + 8;
                a0[0] = w0[o1]; a0[1] = w0[o2]; a0[2] = w0[96 + o1]; a0[3] = w0[96 + o2];
                a1[0] = w1[o1]; a1[1] = w1[o2]; a1[2] = w1[96 + o1]; a1[3] = w1[96 + o2];
                a2[0] = w2[o1]; a2[1] = w2[o2]; a2[2] = w2[96 + o1]; a2[3] = w2[96 + o2];
            }
#pragma unroll
            for (int j = 0; j < 8; j++) {
                int nt = warp * 8 + j;
                int yy = nt & 7, zz = nt >> 3;
                int ro = ((zz + tzi) * 9 + (yy + tyi)) * 12 + g;
                u64 bA = in_b[tg * DC_PAD + ro];
                u64 bB = in_b[tg * DC_PAD + ro + 1];
                u32 b0h = (u32)bA, b0l = (u32)(bA >> 32);
                u32 b1h = (u32)bB, b1l = (u32)(bB >> 32);
                mma16(acc[0][j], a1, b0h, b0l);
                mma16(acc[0][j], a1, b0l, b0h);
                mma16(acc[1][j], a0, b0h, b0l);
                mma16(acc[1][j], a0, b0l, b0h);
                mma16(acc[1][j], a2, b1h, b1l);
                mma16(acc[1][j], a2, b1l, b1h);
            }
        }
        __syncthreads();
    }
    // epilogue: channel-pair interleaved AoS, float2 stores (slots 2g, 2g+1)
    const float bA = s_bias[g], bB = s_bias[g + 8];
#pragma unroll
    for (int px = 0; px < 2; px++)
#pragma unroll
    for (int j = 0; j < 8; j++) {
        int nt = warp * 8 + j;
        int yy = nt & 7, zz = nt >> 3;
        int oz = 2 * (qz0 + zz) + pz, oy = 2 * (qy0 + yy) + py;
        int ox = 2 * (qx0 + 2 * tg) + px;
        int v0 = (oz * 128 + oy) * 128 + ox;
        int v1 = v0 + 2;
        float f0 = acc[px][j][0] + bA, f1 = acc[px][j][1] + bA;
        *(float2*)(g_va + (size_t)v0 * 20 + 2 * g) = make_float2(f0, acc[px][j][2] + bB);
        *(float2*)(g_va + (size_t)v1 * 20 + 2 * g) = make_float2(f1, acc[px][j][3] + bB);
        if (g == 0) { g_dens[v0] = f0; g_dens[v1] = f1; }
    }
}

// ---------------- separable sobel (3 passes, scratch in g_cv) -----------------
__constant__ float c_h[5]  = {0.0625f, 0.25f, 0.375f, 0.25f, 0.0625f};
__constant__ float c_hd[5] = {-0.125f, -0.25f, 0.f, 0.25f, 0.125f};

__global__ void sobel_z(void)
{
    float* sA = (float*)g_cv;
    float* sB = sA + M3;
    int v = blockIdx.x * 256 + threadIdx.x;
    int z = v >> 14;
    float a = 0.f, b = 0.f;
#pragma unroll
    for (int t = 0; t < 5; t++) {
        int zz = z + t - 2;
        if ((unsigned)zz < 128u) {
            float d = g_dens[v + (t - 2) * 16384];
            a += c_h[t] * d;
            b += c_hd[t] * d;
        }
    }
    sA[v] = a; sB[v] = b;
}
__global__ void sobel_y(void)
{
    float* sA = (float*)g_cv;
    float* sB = sA + M3;
    float* AA = sB + M3;
    float* AB = AA + M3;
    float* BA = AB + M3;
    int v = blockIdx.x * 256 + threadIdx.x;
    int y = (v >> 7) & 127;
    float aa = 0.f, ab = 0.f, ba = 0.f;
#pragma unroll
    for (int t = 0; t < 5; t++) {
        int yy = y + t - 2;
        if ((unsigned)yy < 128u) {
            float a = sA[v + (t - 2) * 128];
            float b = sB[v + (t - 2) * 128];
            aa += c_h[t] * a;
            ab += c_hd[t] * a;
            ba += c_h[t] * b;
        }
    }
    AA[v] = aa; AB[v] = ab; BA[v] = ba;
}
__global__ void sobel_x(void)
{
    float* sA = (float*)g_cv;
    float* AA = sA + 2 * M3;
    float* AB = AA + M3;
    float* BA = AB + M3;
    int v = blockIdx.x * 256 + threadIdx.x;
    int x = v & 127;
    float g16 = 0.f, g17 = 0.f, g18 = 0.f;
#pragma unroll
    for (int t = 0; t < 5; t++) {
        int xx = x + t - 2;
        if ((unsigned)xx < 128u) {
            g16 += c_h[t] * BA[v + t - 2];
            g17 += c_h[t] * AB[v + t - 2];
            g18 += c_hd[t] * AA[v + t - 2];
        }
    }
    g_va[(size_t)v * 20 + 16] = g16;
    g_va[(size_t)v * 20 + 17] = g17;
    g_va[(size_t)v * 20 + 18] = g18;
}

// ------------- per-sample: AoS gather (float4), scalar FFMA2 MLP -------------
// AoS slots: slot 2g -> ch g, slot 2g+1 -> ch g+8 (g<8); slots 16..18 grads.
__global__ void __launch_bounds__(128)
sample_kernel(const float* __restrict__ rays_o, const float* __restrict__ rays_d,
              const float* __restrict__ viewdirs,
              const float* __restrict__ w0, const float* __restrict__ b0,
              const float* __restrict__ w1, const float* __restrict__ b1,
              const float* __restrict__ w2, const float* __restrict__ b2,
              const float* __restrict__ w3, const float* __restrict__ b3,
              float* __restrict__ out)
{
    __shared__ __align__(16) float s_wall[58 * 64 + 2 * 64 * 64 + 64 * 3];
    float* s_w0 = s_wall;
    float* s_w1 = s_wall + 58 * 64;
    float* s_w2 = s_w1 + 64 * 64;
    float* s_w3 = s_w2 + 64 * 64;
    const int tid = threadIdx.x;
    for (int i = tid; i < 58 * 64; i += 128) s_w0[i] = w0[i];
    for (int i = tid; i < 64 * 64; i += 128) { s_w1[i] = w1[i]; s_w2[i] = w2[i]; }
    for (int i = tid; i < 192; i += 128) s_w3[i] = w3[i];
    __syncthreads();

    const int stride = gridDim.x * 128;
    for (int idx = blockIdx.x * 128 + tid; idx < BRAYS * NSAMP; idx += stride) {
        int ray = idx / NSAMP;
        int s   = idx - ray * NSAMP;

        float ox = rays_o[ray * 3 + 0], oy = rays_o[ray * 3 + 1], oz = rays_o[ray * 3 + 2];
        float dx = rays_d[ray * 3 + 0], dy = rays_d[ray * 3 + 1], dz = rays_d[ray * 3 + 2];
        float vx = (dx == 0.f) ? 1e-6f : dx;
        float vy = (dy == 0.f) ? 1e-6f : dy;
        float vz = (dz == 0.f) ? 1e-6f : dz;
        float rax = (1.f - ox) / vx, rbx = (-1.f - ox) / vx;
        float ray_ = (1.f - oy) / vy, rby = (-1.f - oy) / vy;
        float raz = (1.f - oz) / vz, rbz = (-1.f - oz) / vz;
        float tmn = fmaxf(fmaxf(fminf(rax, rbx), fminf(ray_, rby)), fminf(raz, rbz));
        float tmx = fminf(fminf(fmaxf(rax, rbx), fmaxf(ray_, rby)), fmaxf(raz, rbz));
        float t_min = fminf(fmaxf(tmn, 0.05f), 2.5f);
        float t_max = fminf(fmaxf(tmx, 0.05f), 2.5f);
        bool mask = (t_max <= t_min);
        float dn = sqrtf(dx * dx + dy * dy + dz * dz);
        float interpx = t_min + STEPV * (float)s / dn;
        float px = ox + dx * interpx, py = oy + dy * interpx, pz = oz + dz * interpx;
        mask = mask || (px < -1.f) || (px > 1.f) || (py < -1.f) || (py > 1.f)
                    || (pz < -1.f) || (pz > 1.f);
        if (mask) {
            g_sdfs[idx] = 100.f;
            if (s == NSAMP - 1) out[BRAYS * 5 + ray] = 0.f;
            continue;
        }
        float fx = fminf(fmaxf((px + 1.f) * 63.5f, 0.f), 127.f);
        float fy = fminf(fmaxf((py + 1.f) * 63.5f, 0.f), 127.f);
        float fz = fminf(fmaxf((pz + 1.f) * 63.5f, 0.f), 127.f);
        int i0x = (int)floorf(fx), i0y = (int)floorf(fy), i0z = (int)floorf(fz);
        int i1x = min(i0x + 1, 127), i1y = min(i0y + 1, 127), i1z = min(i0z + 1, 127);
        float twx = fx - (float)i0x, twy = fy - (float)i0y, twz = fz - (float)i0z;
        float wx0 = 1.f - twx, wy0 = 1.f - twy, wz0 = 1.f - twz;
        int o00 = (i0x * 128 + i0y) * 128;
        int o01 = (i0x * 128 + i1y) * 128;
        int o10 = (i1x * 128 + i0y) * 128;
        int o11 = (i1x * 128 + i1y) * 128;
        int vox[8] = {o00 + i0z, o00 + i1z, o01 + i0z, o01 + i1z,
                      o10 + i0z, o10 + i1z, o11 + i0z, o11 + i1z};
        float wc[8] = {wx0 * wy0 * wz0, wx0 * wy0 * twz,
                       wx0 * twy * wz0, wx0 * twy * twz,
                       twx * wy0 * wz0, twx * wy0 * twz,
                       twx * twy * wz0, twx * twy * twz};
        float samp[19];
#pragma unroll
        for (int c = 0; c < 19; c++) samp[c] = 0.f;
#pragma unroll
        for (int k = 0; k < 8; k++) {
            const float4* p = (const float4*)(g_va + (size_t)vox[k] * 20);
            float4 q0 = __ldg(p), q1 = __ldg(p + 1), q2 = __ldg(p + 2);
            float4 q3 = __ldg(p + 3), q4 = __ldg(p + 4);
            float w = wc[k];
            // slot s<16: even -> ch s/2, odd -> ch s/2+8
            samp[0]  += w * q0.x;  samp[8]  += w * q0.y;
            samp[1]  += w * q0.z;  samp[9]  += w * q0.w;
            samp[2]  += w * q1.x;  samp[10] += w * q1.y;
            samp[3]  += w * q1.z;  samp[11] += w * q1.w;
            samp[4]  += w * q2.x;  samp[12] += w * q2.y;
            samp[5]  += w * q2.z;  samp[13] += w * q2.w;
            samp[6]  += w * q3.x;  samp[14] += w * q3.y;
            samp[7]  += w * q3.z;  samp[15] += w * q3.w;
            samp[16] += w * q4.x;  samp[17] += w * q4.y;
            samp[18] += w * q4.z;
        }
        g_sdfs[idx] = samp[0];
        float gx = samp[16], gy = samp[17], gz = samp[18];
        float gn = sqrtf(gx * gx + gy * gy + gz * gz);
        float inv = 1.f / fmaxf(gn, 1e-12f);
        float nxx = gx * inv, nyy = gy * inv, nzz = gz * inv;
        float ux = viewdirs[ray * 3 + 0], uy = viewdirs[ray * 3 + 1], uz = viewdirs[ray * 3 + 2];
        float dot = -(ux * nxx + uy * nyy + uz * nzz);
        if (s == NSAMP - 1) out[BRAYS * 5 + ray] = -dot;
        float rx = 2.f * dot * nxx + ux;
        float ry = 2.f * dot * nyy + uy;
        float rz = 2.f * dot * nzz + uz;

        float h[58];
#pragma unroll
        for (int c = 0; c < 15; c++) h[c] = samp[1 + c];
        h[15] = dot;
        h[16] = rx; h[17] = ry; h[18] = rz;
        {
            int p = 19;
            float fr = 1.f;
#pragma unroll
            for (int e = 0; e < 6; e++) {
                float sx, cx, sy, cy, sz, cz;
                __sincosf(rx * fr, &sx, &cx);
                __sincosf(ry * fr, &sy, &cy);
                __sincosf(rz * fr, &sz, &cz);
                h[p + 0] = sx; h[p + 1] = sy; h[p + 2] = sz;
                h[p + 3] = cx; h[p + 4] = cy; h[p + 5] = cz;
                p += 6;
                fr *= 2.f;
            }
        }
        h[55] = px; h[56] = py; h[57] = pz;

        u64 acc2[32];
#pragma unroll
        for (int j = 0; j < 32; j++) {
            float2 bb = *(const float2*)(b0 + 2 * j);
            acc2[j] = pack2(bb.x, bb.y);
        }
#pragma unroll 1
        for (int i = 0; i < 58; i++) {
            u64 hv2 = pack2(h[i], h[i]);
            const ulonglong2* wp = (const ulonglong2*)(s_w0 + i * 64);
#pragma unroll
            for (int j = 0; j < 16; j++) {
                ulonglong2 wv = wp[j];
                fma2(acc2[2 * j], hv2, wv.x);
                fma2(acc2[2 * j + 1], hv2, wv.y);
            }
        }
        float act[64];
#pragma unroll
        for (int j = 0; j < 32; j++) {
            float2 p = unpack2(acc2[j]);
            act[2*j] = fmaxf(p.x, 0.f); act[2*j+1] = fmaxf(p.y, 0.f);
            float2 bb = *(const float2*)(b1 + 2 * j);
            acc2[j] = pack2(bb.x, bb.y);
        }
#pragma unroll 1
        for (int i = 0; i < 64; i++) {
            u64 hv2 = pack2(act[i], act[i]);
            const ulonglong2* wp = (const ulonglong2*)(s_w1 + i * 64);
#pragma unroll
            for (int j = 0; j < 16; j++) {
                ulonglong2 wv = wp[j];
                fma2(acc2[2 * j], hv2, wv.x);
                fma2(acc2[2 * j + 1], hv2, wv.y);
            }
        }
#pragma unroll
        for (int j = 0; j < 32; j++) {
            float2 p = unpack2(acc2[j]);
            act[2*j] = fmaxf(p.x, 0.f); act[2*j+1] = fmaxf(p.y, 0.f);
            float2 bb = *(const float2*)(b2 + 2 * j);
            acc2[j] = pack2(bb.x, bb.y);
        }
#pragma unroll 1
        for (int i = 0; i < 64; i++) {
            u64 hv2 = pack2(act[i], act[i]);
            const ulonglong2* wp = (const ulonglong2*)(s_w2 + i * 64);
#pragma unroll
            for (int j = 0; j < 16; j++) {
                ulonglong2 wv = wp[j];
                fma2(acc2[2 * j], hv2, wv.x);
                fma2(acc2[2 * j + 1], hv2, wv.y);
            }
        }
#pragma unroll
        for (int j = 0; j < 32; j++) {
            float2 p = unpack2(acc2[j]);
            act[2*j] = fmaxf(p.x, 0.f); act[2*j+1] = fmaxf(p.y, 0.f);
        }
        float r0 = __ldg(&b3[0]), r1 = __ldg(&b3[1]), r2 = __ldg(&b3[2]);
#pragma unroll 1
        for (int i = 0; i < 64; i++) {
            float hv = act[i];
            r0 += hv * s_w3[i * 3 + 0];
            r1 += hv * s_w3[i * 3 + 1];
            r2 += hv * s_w3[i * 3 + 2];
        }
        g_rgbs[idx * 3 + 0] = r0;
        g_rgbs[idx * 3 + 1] = r1;
        g_rgbs[idx * 3 + 2] = r2;
    }
}

// ---------------- per-ray compositing -----------------------------------------
__global__ void __launch_bounds__(256)
render_kernel(const float* __restrict__ rays_o,
              const float* __restrict__ rays_d,
              const float* __restrict__ variance,
              float* __restrict__ out)
{
    int warp = (blockIdx.x * 256 + threadIdx.x) >> 5;
    int lane = threadIdx.x & 31;
    if (warp >= BRAYS) return;
    int ray = warp;
    float scale = expf(variance[0] * 10.f);
    float ox = rays_o[ray * 3 + 0], oy = rays_o[ray * 3 + 1], oz = rays_o[ray * 3 + 2];
    float dx = rays_d[ray * 3 + 0], dy = rays_d[ray * 3 + 1], dz = rays_d[ray * 3 + 2];
    float vx = (dx == 0.f) ? 1e-6f : dx;
    float vy = (dy == 0.f) ? 1e-6f : dy;
    float vz = (dz == 0.f) ? 1e-6f : dz;
    float rax = (1.f - ox) / vx, rbx = (-1.f - ox) / vx;
    float ray_ = (1.f - oy) / vy, rby = (-1.f - oy) / vy;
    float raz = (1.f - oz) / vz, rbz = (-1.f - oz) / vz;
    float tmn = fmaxf(fmaxf(fminf(rax, rbx), fminf(ray_, rby)), fminf(raz, rbz));
    float t_min = fminf(fmaxf(tmn, 0.05f), 2.5f);
    float dn = sqrtf(dx * dx + dy * dy + dz * dz);
    float base_dist = t_min * dn;

    const float* sd = g_sdfs + ray * NSAMP;
    float T = 1.f, rgb0 = 0.f, rgb1 = 0.f, rgb2 = 0.f, depth = 0.f;

    for (int base = 0; base < NSAMP - 1; base += 32) {
        int s = base + lane;
        bool v = s < NSAMP - 1;
        float alpha = 0.f;
        if (v) {
            float s0 = 1.f / (1.f + expf(-sd[s] * scale));
            float s1 = 1.f / (1.f + expf(-sd[s + 1] * scale));
            alpha = fmaxf((s0 - s1) / (s0 + 1e-10f), 0.f);
        }
        float om = 1.f - alpha;
        float p = om;
#pragma unroll
        for (int off = 1; off < 32; off <<= 1) {
            float t = __shfl_up_sync(0xffffffffu, p, off);
            if (lane >= off) p *= t;
        }
        float excl = __shfl_up_sync(0xffffffffu, p, 1);
        if (lane == 0) excl = 1.f;
        float wgt = T * excl * alpha;
        if (v) {
            out[BRAYS * 6 + ray * (NSAMP - 1) + s] = wgt;
            rgb0 += wgt * g_rgbs[(ray * NSAMP + s) * 3 + 0];
            rgb1 += wgt * g_rgbs[(ray * NSAMP + s) * 3 + 1];
            rgb2 += wgt * g_rgbs[(ray * NSAMP + s) * 3 + 2];
            depth += wgt * (base_dist + STEPV * (float)s);
        }
        T *= __shfl_sync(0xffffffffu, p, 31);
    }
#pragma unroll
    for (int off = 16; off; off >>= 1) {
        rgb0 += __shfl_xor_sync(0xffffffffu, rgb0, off);
        rgb1 += __shfl_xor_sync(0xffffffffu, rgb1, off);
        rgb2 += __shfl_xor_sync(0xffffffffu, rgb2, off);
        depth += __shfl_xor_sync(0xffffffffu, depth, off);
    }
    if (lane == 0) {
        out[ray * 3 + 0] = rgb0;
        out[ray * 3 + 1] = rgb1;
        out[ray * 3 + 2] = rgb2;
        out[BRAYS * 3 + ray] = depth;
        out[BRAYS * 4 + ray] = T;
    }
}

// -----------------------------------------------------------------------------
extern "C" void kernel_launch(void* const* d_in, const int* in_sizes, int n_in,
                              void* d_out, int out_size)
{
    const float* rays_o   = (const float*)d_in[0];
    const float* rays_d   = (const float*)d_in[1];
    const float* viewdirs = (const float*)d_in[2];
    const float* grid     = (const float*)d_in[3];
    const float* c1_w     = (const float*)d_in[4];
    const float* c1_b     = (const float*)d_in[5];
    const float* bn1_g    = (const float*)d_in[6];
    const float* bn1_beta = (const float*)d_in[7];
    const float* bn1_m    = (const float*)d_in[8];
    const float* bn1_v    = (const float*)d_in[9];
    const float* c2_w     = (const float*)d_in[10];
    const float* c2_b     = (const float*)d_in[11];
    const float* bn2_g    = (const float*)d_in[12];
    const float* bn2_beta = (const float*)d_in[13];
    const float* bn2_m    = (const float*)d_in[14];
    const float* bn2_v    = (const float*)d_in[15];
    const float* c3_w     = (const float*)d_in[16];
    const float* c3_b     = (const float*)d_in[17];
    const float* variance = (const float*)d_in[19];
    const float* w0       = (const float*)d_in[20];
    const float* b0       = (const float*)d_in[21];
    const float* w1       = (const float*)d_in[22];
    const float* b1       = (const float*)d_in[23];
    const float* w2       = (const float*)d_in[24];
    const float* b2       = (const float*)d_in[25];
    const float* w3       = (const float*)d_in[26];
    const float* b3       = (const float*)d_in[27];
    float* out = (float*)d_out;

    cudaFuncSetAttribute(conv_tc_kernel<6, 2, 6>,
                         cudaFuncAttributeMaxDynamicSharedMemorySize, CONV_SMEM_P);
    cudaFuncSetAttribute(conv_tc_kernel<38, 10, 38>,
                         cudaFuncAttributeMaxDynamicSharedMemorySize, CONV_SMEM_P);
    cudaFuncSetAttribute(deconv_tc_kernel,
                         cudaFuncAttributeMaxDynamicSharedMemorySize, DC_SMEM);

    prep_all<<<(PREP_TOTAL + 255) / 256, 256>>>(c1_w, c2_w, c3_w, grid);

    dim3 cgrid(8, 8, 16);
    conv_tc_kernel<6, 2, 6><<<cgrid, 512, CONV_SMEM_P>>>(
        c1_b, bn1_g, bn1_beta, bn1_m, bn1_v);
    conv_tc_kernel<38, 10, 38><<<cgrid, 512, CONV_SMEM_P>>>(
        c2_b, bn2_g, bn2_beta, bn2_m, bn2_v);
    deconv_tc_kernel<<<dim3(8, 8, 32), 256, DC_SMEM>>>(c3_b);
    sobel_z<<<M3 / 256, 256>>>();
    sobel_y<<<M3 / 256, 256>>>();
    sobel_x<<<M3 / 256, 256>>>();
    sample_kernel<<<592, 128>>>(rays_o, rays_d, viewdirs,
                                w0, b0, w1, b1, w2, b2, w3, b3, out);
    render_kernel<<<512, 256>>>(rays_o, rays_d, variance, out);
}

// round 17
// speedup vs baseline: 1.0555x; 1.0555x over previous
#include <cuda_runtime.h>
#include <cuda_fp16.h>
#include <math.h>

#define BRAYS 4096
#define NSAMP 447
#define N3 (64*64*64)
#define M3 (128*128*128)
#define STEPV 0.015625f

typedef unsigned long long u64;
typedef unsigned int u32;

__device__ __forceinline__ void fma2(u64& d, u64 a, u64 b) {
    asm("fma.rn.f32x2 %0, %1, %2, %0;" : "+l"(d) : "l"(a), "l"(b));
}
__device__ __forceinline__ u64 pack2(float lo, float hi) {
    u64 r;
    asm("mov.b64 %0, {%1, %2};" : "=l"(r) : "f"(lo), "f"(hi));
    return r;
}
__device__ __forceinline__ float2 unpack2(u64 v) {
    float2 r;
    asm("mov.b64 {%0, %1}, %2;" : "=f"(r.x), "=f"(r.y) : "l"(v));
    return r;
}
__device__ __forceinline__ void mma16(float* c, const u32* a, u32 b0, u32 b1) {
    asm volatile(
        "mma.sync.aligned.m16n8k16.row.col.f32.f16.f16.f32 "
        "{%0,%1,%2,%3},{%4,%5,%6,%7},{%8,%9},{%0,%1,%2,%3};"
        : "+f"(c[0]), "+f"(c[1]), "+f"(c[2]), "+f"(c[3])
        : "r"(a[0]), "r"(a[1]), "r"(a[2]), "r"(a[3]), "r"(b0), "r"(b1));
}
__device__ __forceinline__ u32 packh2(__half a, __half b) {
    __half2 h = __halves2half2(a, b);
    return *(u32*)&h;
}
__device__ __forceinline__ u64 cvpack(float a, float b) {
    __half ha = __float2half_rn(a), hb = __float2half_rn(b);
    __half la = __float2half_rn(a - __half2float(ha));
    __half lb = __float2half_rn(b - __half2float(hb));
    return (u64)packh2(ha, hb) | ((u64)packh2(la, lb) << 32);
}
__device__ __forceinline__ u32 smaddr(const void* p) {
    u32 a;
    asm("{ .reg .u64 t; cvta.to.shared.u64 t, %1; cvt.u32.u64 %0, t; }"
        : "=r"(a) : "l"(p));
    return a;
}
__device__ __forceinline__ void cp_async8(u32 dst, const void* src, int src_sz) {
    asm volatile("cp.async.ca.shared.global [%0], [%1], 8, %2;"
                 :: "r"(dst), "l"(src), "r"(src_sz) : "memory");
}
__device__ __forceinline__ void cp_async16(u32 dst, const void* src) {
    asm volatile("cp.async.cg.shared.global [%0], [%1], 16;"
                 :: "r"(dst), "l"(src) : "memory");
}
__device__ __forceinline__ void cp_async16z(u32 dst, const void* src, int src_sz) {
    asm volatile("cp.async.cg.shared.global [%0], [%1], 16, %2;"
                 :: "r"(dst), "l"(src), "r"(src_sz) : "memory");
}
#define CP_COMMIT() asm volatile("cp.async.commit_group;" ::: "memory")
#define CP_WAIT(n)  asm volatile("cp.async.wait_group %0;" :: "n"(n) : "memory")

__host__ __device__ __forceinline__ int cp_to_ci(int cp, int half) {
    if (cp < 6)  return cp * 2 + half;
    if (cp < 38) { int q = cp - 6;  return 12 + (q >> 3) * 16 + half * 8 + (q & 7); }
    {            int q = cp - 38; return 76 + (q >> 3) * 16 + half * 8 + (q & 7); }
}

// ---------------- scratch -----------------------------------------------------
// AoS slot order: slot 2g = channel g, slot 2g+1 = channel g+8 (g<8);
// slots 16..18 = sobel grads; slot 19 pad.
__device__ float g_dens[M3];
__device__ __align__(16) float g_va[M3 * 20];
__device__ float g_sdfs[BRAYS * NSAMP];
__device__ float g_rgbs[BRAYS * NSAMP * 3];
__device__ __align__(16) u64 g_cv[70 * N3];          // also sobel scratch

#define WCH_H 15552
__device__ __align__(16) u32 g_w1p[2 * WCH_H];
__device__ __align__(16) u32 g_w2p[10 * WCH_H];
#define W3_TOTAL (18*27*2*4*24)
__device__ __align__(16) u32 g_w3p[W3_TOTAL];

// ---- fused prep: weight split + grid convert + rgbs zero ---------------------
#define PREP_W_TOTAL (12 * WCH_H + W3_TOTAL)
#define PREP_CV_TOTAL (6 * N3)
#define PREP_RGB_TOTAL (BRAYS * NSAMP * 3)
#define PREP_TOTAL (PREP_W_TOTAL + PREP_CV_TOTAL + PREP_RGB_TOTAL)
__global__ void prep_all(const float* __restrict__ w1,
                         const float* __restrict__ w2,
                         const float* __restrict__ w3,
                         const float* __restrict__ grid)
{
    int i = blockIdx.x * 256 + threadIdx.x;
    if (i < 12 * WCH_H) {
        const float* w; u32* dst; int CIN; int idx; int conv2;
        if (i < 2 * WCH_H) { w = w1; dst = g_w1p; CIN = 12; idx = i; conv2 = 0; }
        else { w = w2; dst = g_w2p; CIN = 76; idx = i - 2 * WCH_H; conv2 = 1; }
        int ch = idx / WCH_H, r = idx % WCH_H;
        int tap = r / 576, r2 = r % 576;
        int plane = r2 / 288, r3 = r2 % 288;
        int cpl = r3 / 72, co = r3 % 72;
        int cp = ch * 4 + cpl;
        int ci0, ci1;
        if (conv2) { ci0 = (cp < 38) ? cp_to_ci(cp, 0) : 999;
                     ci1 = (cp < 38) ? cp_to_ci(cp, 1) : 999; }
        else       { ci0 = 2 * cp; ci1 = 2 * cp + 1; }
        float v0 = (co < 64 && ci0 < CIN) ? __ldg(&w[co * (CIN * 27) + ci0 * 27 + tap]) : 0.f;
        float v1 = (co < 64 && ci1 < CIN) ? __ldg(&w[co * (CIN * 27) + ci1 * 27 + tap]) : 0.f;
        __half h0 = __float2half_rn(v0);
        __half l0 = __float2half_rn(v0 - __half2float(h0));
        __half h1 = __float2half_rn(v1);
        __half l1 = __float2half_rn(v1 - __half2float(h1));
        dst[idx] = plane ? packh2(l0, l1) : packh2(h0, h1);
        return;
    }
    if (i < PREP_W_TOTAL) {
        int idx = i - 12 * WCH_H;
        int co = idx % 24; int t = idx / 24;
        int cpl = t % 4; t /= 4;
        int plane = t % 2; t /= 2;
        int tap = t % 27; int ch = t / 27;
        int kz = tap / 9, ky = (tap / 3) % 3, kx = tap % 3;
        int cp = ch * 4 + cpl;
        float v0 = 0.f, v1 = 0.f;
        if (co < 16 && cp < 70) {
            int ci0 = cp_to_ci(cp, 0), ci1 = cp_to_ci(cp, 1);
            int foff = co * 27 + (2 - kz) * 9 + (2 - ky) * 3 + (2 - kx);
            v0 = __ldg(&w3[ci0 * (16 * 27) + foff]);
            v1 = __ldg(&w3[ci1 * (16 * 27) + foff]);
        }
        __half h0 = __float2half_rn(v0);
        __half l0 = __float2half_rn(v0 - __half2float(h0));
        __half h1 = __float2half_rn(v1);
        __half l1 = __float2half_rn(v1 - __half2float(h1));
        g_w3p[idx] = plane ? packh2(l0, l1) : packh2(h0, h1);
        return;
    }
    if (i < PREP_W_TOTAL + PREP_CV_TOTAL) {
        int idx = i - PREP_W_TOTAL;
        int cp = idx / N3, v = idx - cp * N3;
        float v0 = __ldg(&grid[(2 * cp) * N3 + v]);
        float v1 = __ldg(&grid[(2 * cp + 1) * N3 + v]);
        g_cv[cp * N3 + v] = cvpack(v0, v1);
        return;
    }
    int idx = i - PREP_W_TOTAL - PREP_CV_TOTAL;
    if (idx < PREP_RGB_TOTAL) g_rgbs[idx] = 0.f;
}

// ======== pipelined tensor-core 3x3x3 conv + BN + ReLU (8x8x4 tile) =========
#define CIN_PAD4 724
#define CONV_SMEM_P (8*CIN_PAD4*8 + 2*WCH_H*4)   // 170752 B
template<int NCP, int NCH, int CPBASE>
__global__ void __launch_bounds__(512) conv_tc_kernel(
    const float* __restrict__ cb,
    const float* __restrict__ bg, const float* __restrict__ bb,
    const float* __restrict__ bm, const float* __restrict__ bv)
{
    extern __shared__ u64 smem64[];
    u64* s_in0 = smem64;
    u64* s_in1 = smem64 + 4 * CIN_PAD4;
    u32* s_w0  = (u32*)(smem64 + 8 * CIN_PAD4);
    u32* s_w1  = s_w0 + WCH_H;
    __shared__ float s_a[64], s_c[64];
    const u32* wp = (CPBASE == 6) ? g_w1p : g_w2p;

    const int tid = threadIdx.x;
    const int x0 = blockIdx.x * 8, y0 = blockIdx.y * 8, z0 = blockIdx.z * 4;
    if (tid < 64) {
        float s = bg[tid] * rsqrtf(bv[tid] + 1e-5f);
        s_a[tid] = s;
        s_c[tid] = cb[tid] * s + bb[tid] - bm[tid] * s;
    }
    const int warp = tid >> 5, lane = tid & 31;
    const int g = lane >> 2, tg = lane & 3;
    const int coh = (warp & 1) * 32;
    const int q4  = (warp >> 1) * 4;

    float acc[2][4][4];
#pragma unroll
    for (int m = 0; m < 2; m++)
#pragma unroll
        for (int j = 0; j < 4; j++)
#pragma unroll
            for (int c = 0; c < 4; c++) acc[m][j][c] = 0.f;

    auto stage = [&](int ch, int buf) {
        u64* dst_in = buf ? s_in1 : s_in0;
        u32* dst_w  = buf ? s_w1 : s_w0;
        for (int i = tid; i < 4 * 720; i += 512) {
            int cpl = i / 720, rem = i - cpl * 720;
            int z = rem / 120, rem2 = rem - z * 120;
            int y = rem2 / 12, x = rem2 - y * 12;
            int gx = x0 - 1 + x, gy = y0 - 1 + y, gz = z0 - 1 + z;
            int cp = ch * 4 + cpl;
            bool ok = (x < 10) && cp < NCP && (unsigned)gx < 64u
                      && (unsigned)gy < 64u && (unsigned)gz < 64u;
            const u64* src = ok ? &g_cv[cp * N3 + (gz * 64 + gy) * 64 + gx] : &g_cv[0];
            cp_async8(smaddr(&dst_in[cpl * CIN_PAD4 + z * 120 + y * 12 + x]),
                      src, ok ? 8 : 0);
        }
        const float4* ws4 = (const float4*)(wp + ch * WCH_H);
        float4* wd4 = (float4*)dst_w;
        for (int i = tid; i < WCH_H / 4; i += 512)
            cp_async16(smaddr(&wd4[i]), &ws4[i]);
    };

    stage(0, 0);
    CP_COMMIT();
    for (int ch = 0; ch < NCH; ch++) {
        int buf = ch & 1;
        if (ch + 1 < NCH) {
            stage(ch + 1, buf ^ 1);
            CP_COMMIT();
            CP_WAIT(1);
        } else {
            CP_WAIT(0);
        }
        __syncthreads();
        const u64* in_b = buf ? s_in1 : s_in0;
        const u32* w_b  = buf ? s_w1 : s_w0;
#pragma unroll 1
        for (int tap = 0; tap < 27; tap++) {
            int kz = tap / 9, ky = (tap / 3) % 3, kx = tap % 3;
            const u32* wb = w_b + tap * 576;
            u32 a[2][4];
#pragma unroll
            for (int mg = 0; mg < 2; mg++) {
                int c0g = coh + 16 * mg + g;
                a[mg][0] = wb[tg * 72 + c0g];
                a[mg][1] = wb[tg * 72 + c0g + 8];
                a[mg][2] = wb[(4 + tg) * 72 + c0g];
                a[mg][3] = wb[(4 + tg) * 72 + c0g + 8];
            }
#pragma unroll
            for (int j = 0; j < 4; j++) {
                int nt = q4 + j;
                int yy = nt & 7, zz = nt >> 3;
                int ro = ((zz + kz) * 10 + yy + ky) * 12 + g + kx;
                u64 b = in_b[tg * CIN_PAD4 + ro];
                u32 b0 = (u32)b, b1 = (u32)(b >> 32);
                mma16(acc[0][j], a[0], b0, b1);
                mma16(acc[1][j], a[1], b0, b1);
                mma16(acc[0][j], a[0], b1, b0);
                mma16(acc[1][j], a[1], b1, b0);
            }
        }
        __syncthreads();
    }
#pragma unroll
    for (int mg = 0; mg < 2; mg++) {
        int c0 = coh + 16 * mg;
        int coA = c0 + g, coB = c0 + g + 8;
        float aA = s_a[coA], cA = s_c[coA];
        float aB = s_a[coB], cB = s_c[coB];
        int cp = CPBASE + (c0 >> 4) * 8 + g;
#pragma unroll
        for (int j = 0; j < 4; j++) {
            int nt = q4 + j;
            int y = nt & 7, z = nt >> 3;
            int vb = ((z0 + z) * 64 + (y0 + y)) * 64 + x0 + 2 * tg;
            float* c = acc[mg][j];
            float vA0 = fmaxf(c[0] * aA + cA, 0.f);
            float vA1 = fmaxf(c[1] * aA + cA, 0.f);
            float vB0 = fmaxf(c[2] * aB + cB, 0.f);
            float vB1 = fmaxf(c[3] * aB + cB, 0.f);
            g_cv[cp * N3 + vb]     = cvpack(vA0, vB0);
            g_cv[cp * N3 + vb + 1] = cvpack(vA1, vB1);
        }
    }
}

// ======== pipelined tensor-core transposed conv (2 x-parity classes) ========
// blockIdx.z = qz*4 + pyz so the 4 pyz blocks sharing a tile are launch-adjacent
// (L2 reuse). Row staging in 16B granules.
#define DC_PAD 980
#define DC_SMEM (2*4*DC_PAD*8 + 2*12*192*4)   // 81152 B
__global__ void __launch_bounds__(256) deconv_tc_kernel(const float* __restrict__ cb)
{
    extern __shared__ u64 dsm[];
    u64* s_in0 = dsm;
    u64* s_in1 = dsm + 4 * DC_PAD;
    u32* s_wa  = (u32*)(dsm + 8 * DC_PAD);
    u32* s_wb  = s_wa + 12 * 192;
    __shared__ float s_bias[16];
    const int tid = threadIdx.x;
    const int qx0 = blockIdx.x * 8, qy0 = blockIdx.y * 8;
    const int qz0 = (blockIdx.z >> 2) * 8;
    const int pyz = blockIdx.z & 3;
    const int py = pyz & 1, pz = pyz >> 1;
    if (tid < 16) s_bias[tid] = __ldg(&cb[tid]);

    const int nyl = 1 + py, nzl = 1 + pz;
    const int ntapw = 3 * nyl * nzl;
    const bool x8ok = (qx0 < 56);

    const int warp = tid >> 5, lane = tid & 31;
    const int g = lane >> 2, tg = lane & 3;

    const int row0 = tid;                   // rows tid and tid+256 (if < 324)
    float acc[2][8][4];
#pragma unroll
    for (int m = 0; m < 2; m++)
#pragma unroll
        for (int j = 0; j < 8; j++)
#pragma unroll
            for (int c = 0; c < 4; c++) acc[m][j][c] = 0.f;

    auto stage = [&](int ch, int buf) {
        u64* dst_in = buf ? s_in1 : s_in0;
        u32* dst_w  = buf ? s_wb : s_wa;
#pragma unroll
        for (int rr = 0; rr < 2; rr++) {
            int r = row0 + rr * 256;
            if (r < 324) {
                int cpl = r / 81, rem = r - cpl * 81;
                int z = rem / 9, y = rem - z * 9;
                int gy = qy0 + y, gz = qz0 + z;
                int cp = ch * 4 + cpl;
                bool rowOk = (gy < 64) && (gz < 64) && (cp < 70);
                const u64* src = rowOk ? &g_cv[cp * N3 + (gz * 64 + gy) * 64 + qx0]
                                       : &g_cv[0];
                u32 d = smaddr(&dst_in[cpl * DC_PAD + (z * 9 + y) * 12]);
                int sz16 = rowOk ? 16 : 0;
#pragma unroll
                for (int q = 0; q < 4; q++)
                    cp_async16z(d + 16 * q, src + (rowOk ? 2 * q : 0), sz16);
                cp_async8(d + 64, src + (rowOk ? 8 : 0), (rowOk && x8ok) ? 8 : 0);
            }
        }
        for (int i = tid; i < ntapw * 48; i += 256) {
            int t = i / 48, r4 = i - t * 48;
            int kxi = t % 3, q = t / 3;
            int tyi = q % nyl, tzi = q / nyl;
            int ky = py ? tyi * 2 : 1;
            int kz = pz ? tzi * 2 : 1;
            const float4* src = (const float4*)(g_w3p + (ch * 27 + kz * 9 + ky * 3 + kxi) * 192);
            cp_async16(smaddr((float4*)dst_w + t * 48 + r4), src + r4);
        }
    };

    stage(0, 0);
    CP_COMMIT();
    for (int ch = 0; ch < 18; ch++) {
        int buf = ch & 1;
        if (ch + 1 < 18) {
            stage(ch + 1, buf ^ 1);
            CP_COMMIT();
            CP_WAIT(1);
        } else {
            CP_WAIT(0);
        }
        __syncthreads();
        const u64* in_b = buf ? s_in1 : s_in0;
        const u32* s_w  = buf ? s_wb : s_wa;
        for (int tzi = 0; tzi < nzl; tzi++)
        for (int tyi = 0; tyi < nyl; tyi++) {
            int t3 = (tzi * nyl + tyi) * 3;
            u32 a0[4], a1[4], a2[4];
            {
                const u32* w0 = s_w + t3 * 192;
                const u32* w1 = w0 + 192;
                const u32* w2 = w1 + 192;
                int o1 = tg * 24 + g, o2 = o1 + 8;
                a0[0] = w0[o1]; a0[1] = w0[o2]; a0[2] = w0[96 + o1]; a0[3] = w0[96 + o2];
                a1[0] = w1[o1]; a1[1] = w1[o2]; a1[2] = w1[96 + o1]; a1[3] = w1[96 + o2];
                a2[0] = w2[o1]; a2[1] = w2[o2]; a2[2] = w2[96 + o1]; a2[3] = w2[96 + o2];
            }
#pragma unroll
            for (int j = 0; j < 8; j++) {
                int nt = warp * 8 + j;
                int yy = nt & 7, zz = nt >> 3;
                int ro = ((zz + tzi) * 9 + (yy + tyi)) * 12 + g;
                u64 bA = in_b[tg * DC_PAD + ro];
                u64 bB = in_b[tg * DC_PAD + ro + 1];
                u32 b0h = (u32)bA, b0l = (u32)(bA >> 32);
                u32 b1h = (u32)bB, b1l = (u32)(bB >> 32);
                mma16(acc[0][j], a1, b0h, b0l);
                mma16(acc[0][j], a1, b0l, b0h);
                mma16(acc[1][j], a0, b0h, b0l);
                mma16(acc[1][j], a0, b0l, b0h);
                mma16(acc[1][j], a2, b1h, b1l);
                mma16(acc[1][j], a2, b1l, b1h);
            }
        }
        __syncthreads();
    }
    // epilogue: channel-pair interleaved AoS, float2 stores (slots 2g, 2g+1)
    const float bA = s_bias[g], bB = s_bias[g + 8];
#pragma unroll
    for (int px = 0; px < 2; px++)
#pragma unroll
    for (int j = 0; j < 8; j++) {
        int nt = warp * 8 + j;
        int yy = nt & 7, zz = nt >> 3;
        int oz = 2 * (qz0 + zz) + pz, oy = 2 * (qy0 + yy) + py;
        int ox = 2 * (qx0 + 2 * tg) + px;
        int v0 = (oz * 128 + oy) * 128 + ox;
        int v1 = v0 + 2;
        float f0 = acc[px][j][0] + bA, f1 = acc[px][j][1] + bA;
        *(float2*)(g_va + (size_t)v0 * 20 + 2 * g) = make_float2(f0, acc[px][j][2] + bB);
        *(float2*)(g_va + (size_t)v1 * 20 + 2 * g) = make_float2(f1, acc[px][j][3] + bB);
        if (g == 0) { g_dens[v0] = f0; g_dens[v1] = f1; }
    }
}

// ---------------- separable sobel (3 passes, scratch in g_cv) -----------------
__constant__ float c_h[5]  = {0.0625f, 0.25f, 0.375f, 0.25f, 0.0625f};
__constant__ float c_hd[5] = {-0.125f, -0.25f, 0.f, 0.25f, 0.125f};

__global__ void sobel_z(void)
{
    float* sA = (float*)g_cv;
    float* sB = sA + M3;
    int v = blockIdx.x * 256 + threadIdx.x;
    int z = v >> 14;
    float a = 0.f, b = 0.f;
#pragma unroll
    for (int t = 0; t < 5; t++) {
        int zz = z + t - 2;
        if ((unsigned)zz < 128u) {
            float d = g_dens[v + (t - 2) * 16384];
            a += c_h[t] * d;
            b += c_hd[t] * d;
        }
    }
    sA[v] = a; sB[v] = b;
}
__global__ void sobel_y(void)
{
    float* sA = (float*)g_cv;
    float* sB = sA + M3;
    float* AA = sB + M3;
    float* AB = AA + M3;
    float* BA = AB + M3;
    int v = blockIdx.x * 256 + threadIdx.x;
    int y = (v >> 7) & 127;
    float aa = 0.f, ab = 0.f, ba = 0.f;
#pragma unroll
    for (int t = 0; t < 5; t++) {
        int yy = y + t - 2;
        if ((unsigned)yy < 128u) {
            float a = sA[v + (t - 2) * 128];
            float b = sB[v + (t - 2) * 128];
            aa += c_h[t] * a;
            ab += c_hd[t] * a;
            ba += c_h[t] * b;
        }
    }
    AA[v] = aa; AB[v] = ab; BA[v] = ba;
}
__global__ void sobel_x(void)
{
    float* sA = (float*)g_cv;
    float* AA = sA + 2 * M3;
    float* AB = AA + M3;
    float* BA = AB + M3;
    int v = blockIdx.x * 256 + threadIdx.x;
    int x = v & 127;
    float g16 = 0.f, g17 = 0.f, g18 = 0.f;
#pragma unroll
    for (int t = 0; t < 5; t++) {
        int xx = x + t - 2;
        if ((unsigned)xx < 128u) {
            g16 += c_h[t] * BA[v + t - 2];
            g17 += c_h[t] * AB[v + t - 2];
            g18 += c_hd[t] * AA[v + t - 2];
        }
    }
    g_va[(size_t)v * 20 + 16] = g16;
    g_va[(size_t)v * 20 + 17] = g17;
    g_va[(size_t)v * 20 + 18] = g18;
}

// ------------- per-sample: AoS gather (float4), scalar FFMA2 MLP -------------
__global__ void __launch_bounds__(128)
sample_kernel(const float* __restrict__ rays_o, const float* __restrict__ rays_d,
              const float* __restrict__ viewdirs,
              const float* __restrict__ w0, const float* __restrict__ b0,
              const float* __restrict__ w1, const float* __restrict__ b1,
              const float* __restrict__ w2, const float* __restrict__ b2,
              const float* __restrict__ w3, const float* __restrict__ b3,
              float* __restrict__ out)
{
    __shared__ __align__(16) float s_wall[58 * 64 + 2 * 64 * 64 + 64 * 3];
    float* s_w0 = s_wall;
    float* s_w1 = s_wall + 58 * 64;
    float* s_w2 = s_w1 + 64 * 64;
    float* s_w3 = s_w2 + 64 * 64;
    const int tid = threadIdx.x;
    for (int i = tid; i < 58 * 64; i += 128) s_w0[i] = w0[i];
    for (int i = tid; i < 64 * 64; i += 128) { s_w1[i] = w1[i]; s_w2[i] = w2[i]; }
    for (int i = tid; i < 192; i += 128) s_w3[i] = w3[i];
    __syncthreads();

    const int stride = gridDim.x * 128;
    for (int idx = blockIdx.x * 128 + tid; idx < BRAYS * NSAMP; idx += stride) {
        int ray = idx / NSAMP;
        int s   = idx - ray * NSAMP;

        float ox = rays_o[ray * 3 + 0], oy = rays_o[ray * 3 + 1], oz = rays_o[ray * 3 + 2];
        float dx = rays_d[ray * 3 + 0], dy = rays_d[ray * 3 + 1], dz = rays_d[ray * 3 + 2];
        float vx = (dx == 0.f) ? 1e-6f : dx;
        float vy = (dy == 0.f) ? 1e-6f : dy;
        float vz = (dz == 0.f) ? 1e-6f : dz;
        float rax = (1.f - ox) / vx, rbx = (-1.f - ox) / vx;
        float ray_ = (1.f - oy) / vy, rby = (-1.f - oy) / vy;
        float raz = (1.f - oz) / vz, rbz = (-1.f - oz) / vz;
        float tmn = fmaxf(fmaxf(fminf(rax, rbx), fminf(ray_, rby)), fminf(raz, rbz));
        float tmx = fminf(fminf(fmaxf(rax, rbx), fmaxf(ray_, rby)), fmaxf(raz, rbz));
        float t_min = fminf(fmaxf(tmn, 0.05f), 2.5f);
        float t_max = fminf(fmaxf(tmx, 0.05f), 2.5f);
        bool mask = (t_max <= t_min);
        float dn = sqrtf(dx * dx + dy * dy + dz * dz);
        float interpx = t_min + STEPV * (float)s / dn;
        float px = ox + dx * interpx, py = oy + dy * interpx, pz = oz + dz * interpx;
        mask = mask || (px < -1.f) || (px > 1.f) || (py < -1.f) || (py > 1.f)
                    || (pz < -1.f) || (pz > 1.f);
        if (mask) {
            g_sdfs[idx] = 100.f;
            if (s == NSAMP - 1) out[BRAYS * 5 + ray] = 0.f;
            continue;
        }
        float fx = fminf(fmaxf((px + 1.f) * 63.5f, 0.f), 127.f);
        float fy = fminf(fmaxf((py + 1.f) * 63.5f, 0.f), 127.f);
        float fz = fminf(fmaxf((pz + 1.f) * 63.5f, 0.f), 127.f);
        int i0x = (int)floorf(fx), i0y = (int)floorf(fy), i0z = (int)floorf(fz);
        int i1x = min(i0x + 1, 127), i1y = min(i0y + 1, 127), i1z = min(i0z + 1, 127);
        float twx = fx - (float)i0x, twy = fy - (float)i0y, twz = fz - (float)i0z;
        float wx0 = 1.f - twx, wy0 = 1.f - twy, wz0 = 1.f - twz;
        int o00 = (i0x * 128 + i0y) * 128;
        int o01 = (i0x * 128 + i1y) * 128;
        int o10 = (i1x * 128 + i0y) * 128;
        int o11 = (i1x * 128 + i1y) * 128;
        int vox[8] = {o00 + i0z, o00 + i1z, o01 + i0z, o01 + i1z,
                      o10 + i0z, o10 + i1z, o11 + i0z, o11 + i1z};
        float wc[8] = {wx0 * wy0 * wz0, wx0 * wy0 * twz,
                       wx0 * twy * wz0, wx0 * twy * twz,
                       twx * wy0 * wz0, twx * wy0 * twz,
                       twx * twy * wz0, twx * twy * twz};
        float samp[19];
#pragma unroll
        for (int c = 0; c < 19; c++) samp[c] = 0.f;
#pragma unroll
        for (int k = 0; k < 8; k++) {
            const float4* p = (const float4*)(g_va + (size_t)vox[k] * 20);
            float4 q0 = __ldg(p), q1 = __ldg(p + 1), q2 = __ldg(p + 2);
            float4 q3 = __ldg(p + 3), q4 = __ldg(p + 4);
            float w = wc[k];
            samp[0]  += w * q0.x;  samp[8]  += w * q0.y;
            samp[1]  += w * q0.z;  samp[9]  += w * q0.w;
            samp[2]  += w * q1.x;  samp[10] += w * q1.y;
            samp[3]  += w * q1.z;  samp[11] += w * q1.w;
            samp[4]  += w * q2.x;  samp[12] += w * q2.y;
            samp[5]  += w * q2.z;  samp[13] += w * q2.w;
            samp[6]  += w * q3.x;  samp[14] += w * q3.y;
            samp[7]  += w * q3.z;  samp[15] += w * q3.w;
            samp[16] += w * q4.x;  samp[17] += w * q4.y;
            samp[18] += w * q4.z;
        }
        g_sdfs[idx] = samp[0];
        float gx = samp[16], gy = samp[17], gz = samp[18];
        float gn = sqrtf(gx * gx + gy * gy + gz * gz);
        float inv = 1.f / fmaxf(gn, 1e-12f);
        float nxx = gx * inv, nyy = gy * inv, nzz = gz * inv;
        float ux = viewdirs[ray * 3 + 0], uy = viewdirs[ray * 3 + 1], uz = viewdirs[ray * 3 + 2];
        float dot = -(ux * nxx + uy * nyy + uz * nzz);
        if (s == NSAMP - 1) out[BRAYS * 5 + ray] = -dot;
        float rx = 2.f * dot * nxx + ux;
        float ry = 2.f * dot * nyy + uy;
        float rz = 2.f * dot * nzz + uz;

        float h[58];
#pragma unroll
        for (int c = 0; c < 15; c++) h[c] = samp[1 + c];
        h[15] = dot;
        h[16] = rx; h[17] = ry; h[18] = rz;
        {
            int p = 19;
            float fr = 1.f;
#pragma unroll
            for (int e = 0; e < 6; e++) {
                float sx, cx, sy, cy, sz, cz;
                __sincosf(rx * fr, &sx, &cx);
                __sincosf(ry * fr, &sy, &cy);
                __sincosf(rz * fr, &sz, &cz);
                h[p + 0] = sx; h[p + 1] = sy; h[p + 2] = sz;
                h[p + 3] = cx; h[p + 4] = cy; h[p + 5] = cz;
                p += 6;
                fr *= 2.f;
            }
        }
        h[55] = px; h[56] = py; h[57] = pz;

        u64 acc2[32];
#pragma unroll
        for (int j = 0; j < 32; j++) {
            float2 bb = *(const float2*)(b0 + 2 * j);
            acc2[j] = pack2(bb.x, bb.y);
        }
#pragma unroll 1
        for (int i = 0; i < 58; i++) {
            u64 hv2 = pack2(h[i], h[i]);
            const ulonglong2* wp = (const ulonglong2*)(s_w0 + i * 64);
#pragma unroll
            for (int j = 0; j < 16; j++) {
                ulonglong2 wv = wp[j];
                fma2(acc2[2 * j], hv2, wv.x);
                fma2(acc2[2 * j + 1], hv2, wv.y);
            }
        }
        float act[64];
#pragma unroll
        for (int j = 0; j < 32; j++) {
            float2 p = unpack2(acc2[j]);
            act[2*j] = fmaxf(p.x, 0.f); act[2*j+1] = fmaxf(p.y, 0.f);
            float2 bb = *(const float2*)(b1 + 2 * j);
            acc2[j] = pack2(bb.x, bb.y);
        }
#pragma unroll 1
        for (int i = 0; i < 64; i++) {
            u64 hv2 = pack2(act[i], act[i]);
            const ulonglong2* wp = (const ulonglong2*)(s_w1 + i * 64);
#pragma unroll
            for (int j = 0; j < 16; j++) {
                ulonglong2 wv = wp[j];
                fma2(acc2[2 * j], hv2, wv.x);
                fma2(acc2[2 * j + 1], hv2, wv.y);
            }
        }
#pragma unroll
        for (int j = 0; j < 32; j++) {
            float2 p = unpack2(acc2[j]);
            act[2*j] = fmaxf(p.x, 0.f); act[2*j+1] = fmaxf(p.y, 0.f);
            float2 bb = *(const float2*)(b2 + 2 * j);
            acc2[j] = pack2(bb.x, bb.y);
        }
#pragma unroll 1
        for (int i = 0; i < 64; i++) {
            u64 hv2 = pack2(act[i], act[i]);
            const ulonglong2* wp = (const ulonglong2*)(s_w2 + i * 64);
#pragma unroll
            for (int j = 0; j < 16; j++) {
                ulonglong2 wv = wp[j];
                fma2(acc2[2 * j], hv2, wv.x);
                fma2(acc2[2 * j + 1], hv2, wv.y);
            }
        }
#pragma unroll
        for (int j = 0; j < 32; j++) {
            float2 p = unpack2(acc2[j]);
            act[2*j] = fmaxf(p.x, 0.f); act[2*j+1] = fmaxf(p.y, 0.f);
        }
        float r0 = __ldg(&b3[0]), r1 = __ldg(&b3[1]), r2 = __ldg(&b3[2]);
#pragma unroll 1
        for (int i = 0; i < 64; i++) {
            float hv = act[i];
            r0 += hv * s_w3[i * 3 + 0];
            r1 += hv * s_w3[i * 3 + 1];
            r2 += hv * s_w3[i * 3 + 2];
        }
        g_rgbs[idx * 3 + 0] = r0;
        g_rgbs[idx * 3 + 1] = r1;
        g_rgbs[idx * 3 + 2] = r2;
    }
}

// ---------------- per-ray compositing -----------------------------------------
__global__ void __launch_bounds__(256)
render_kernel(const float* __restrict__ rays_o,
              const float* __restrict__ rays_d,
              const float* __restrict__ variance,
              float* __restrict__ out)
{
    int warp = (blockIdx.x * 256 + threadIdx.x) >> 5;
    int lane = threadIdx.x & 31;
    if (warp >= BRAYS) return;
    int ray = warp;
    float scale = expf(variance[0] * 10.f);
    float ox = rays_o[ray * 3 + 0], oy = rays_o[ray * 3 + 1], oz = rays_o[ray * 3 + 2];
    float dx = rays_d[ray * 3 + 0], dy = rays_d[ray * 3 + 1], dz = rays_d[ray * 3 + 2];
    float vx = (dx == 0.f) ? 1e-6f : dx;
    float vy = (dy == 0.f) ? 1e-6f : dy;
    float vz = (dz == 0.f) ? 1e-6f : dz;
    float rax = (1.f - ox) / vx, rbx = (-1.f - ox) / vx;
    float ray_ = (1.f - oy) / vy, rby = (-1.f - oy) / vy;
    float raz = (1.f - oz) / vz, rbz = (-1.f - oz) / vz;
    float tmn = fmaxf(fmaxf(fminf(rax, rbx), fminf(ray_, rby)), fminf(raz, rbz));
    float t_min = fminf(fmaxf(tmn, 0.05f), 2.5f);
    float dn = sqrtf(dx * dx + dy * dy + dz * dz);
    float base_dist = t_min * dn;

    const float* sd = g_sdfs + ray * NSAMP;
    float T = 1.f, rgb0 = 0.f, rgb1 = 0.f, rgb2 = 0.f, depth = 0.f;

    for (int base = 0; base < NSAMP - 1; base += 32) {
        int s = base + lane;
        bool v = s < NSAMP - 1;
        float alpha = 0.f;
        if (v) {
            float s0 = 1.f / (1.f + expf(-sd[s] * scale));
            float s1 = 1.f / (1.f + expf(-sd[s + 1] * scale));
            alpha = fmaxf((s0 - s1) / (s0 + 1e-10f), 0.f);
        }
        float om = 1.f - alpha;
        float p = om;
#pragma unroll
        for (int off = 1; off < 32; off <<= 1) {
            float t = __shfl_up_sync(0xffffffffu, p, off);
            if (lane >= off) p *= t;
        }
        float excl = __shfl_up_sync(0xffffffffu, p, 1);
        if (lane == 0) excl = 1.f;
        float wgt = T * excl * alpha;
        if (v) {
            out[BRAYS * 6 + ray * (NSAMP - 1) + s] = wgt;
            rgb0 += wgt * g_rgbs[(ray * NSAMP + s) * 3 + 0];
            rgb1 += wgt * g_rgbs[(ray * NSAMP + s) * 3 + 1];
            rgb2 += wgt * g_rgbs[(ray * NSAMP + s) * 3 + 2];
            depth += wgt * (base_dist + STEPV * (float)s);
        }
        T *= __shfl_sync(0xffffffffu, p, 31);
    }
#pragma unroll
    for (int off = 16; off; off >>= 1) {
        rgb0 += __shfl_xor_sync(0xffffffffu, rgb0, off);
        rgb1 += __shfl_xor_sync(0xffffffffu, rgb1, off);
        rgb2 += __shfl_xor_sync(0xffffffffu, rgb2, off);
        depth += __shfl_xor_sync(0xffffffffu, depth, off);
    }
    if (lane == 0) {
        out[ray * 3 + 0] = rgb0;
        out[ray * 3 + 1] = rgb1;
        out[ray * 3 + 2] = rgb2;
        out[BRAYS * 3 + ray] = depth;
        out[BRAYS * 4 + ray] = T;
    }
}

// -----------------------------------------------------------------------------
extern "C" void kernel_launch(void* const* d_in, const int* in_sizes, int n_in,
                              void* d_out, int out_size)
{
    const float* rays_o   = (const float*)d_in[0];
    const float* rays_d   = (const float*)d_in[1];
    const float* viewdirs = (const float*)d_in[2];
    const float* grid     = (const float*)d_in[3];
    const float* c1_w     = (const float*)d_in[4];
    const float* c1_b     = (const float*)d_in[5];
    const float* bn1_g    = (const float*)d_in[6];
    const float* bn1_beta = (const float*)d_in[7];
    const float* bn1_m    = (const float*)d_in[8];
    const float* bn1_v    = (const float*)d_in[9];
    const float* c2_w     = (const float*)d_in[10];
    const float* c2_b     = (const float*)d_in[11];
    const float* bn2_g    = (const float*)d_in[12];
    const float* bn2_beta = (const float*)d_in[13];
    const float* bn2_m    = (const float*)d_in[14];
    const float* bn2_v    = (const float*)d_in[15];
    const float* c3_w     = (const float*)d_in[16];
    const float* c3_b     = (const float*)d_in[17];
    const float* variance = (const float*)d_in[19];
    const float* w0       = (const float*)d_in[20];
    const float* b0       = (const float*)d_in[21];
    const float* w1       = (const float*)d_in[22];
    const float* b1       = (const float*)d_in[23];
    const float* w2       = (const float*)d_in[24];
    const float* b2       = (const float*)d_in[25];
    const float* w3       = (const float*)d_in[26];
    const float* b3       = (const float*)d_in[27];
    float* out = (float*)d_out;

    cudaFuncSetAttribute(conv_tc_kernel<6, 2, 6>,
                         cudaFuncAttributeMaxDynamicSharedMemorySize, CONV_SMEM_P);
    cudaFuncSetAttribute(conv_tc_kernel<38, 10, 38>,
                         cudaFuncAttributeMaxDynamicSharedMemorySize, CONV_SMEM_P);
    cudaFuncSetAttribute(deconv_tc_kernel,
                         cudaFuncAttributeMaxDynamicSharedMemorySize, DC_SMEM);

    prep_all<<<(PREP_TOTAL + 255) / 256, 256>>>(c1_w, c2_w, c3_w, grid);

    dim3 cgrid(8, 8, 16);
    conv_tc_kernel<6, 2, 6><<<cgrid, 512, CONV_SMEM_P>>>(
        c1_b, bn1_g, bn1_beta, bn1_m, bn1_v);
    conv_tc_kernel<38, 10, 38><<<cgrid, 512, CONV_SMEM_P>>>(
        c2_b, bn2_g, bn2_beta, bn2_m, bn2_v);
    deconv_tc_kernel<<<dim3(8, 8, 32), 256, DC_SMEM>>>(c3_b);
    sobel_z<<<M3 / 256, 256>>>();
    sobel_y<<<M3 / 256, 256>>>();
    sobel_x<<<M3 / 256, 256>>>();
    sample_kernel<<<592, 128>>>(rays_o, rays_d, viewdirs,
                                w0, b0, w1, b1, w2, b2, w3, b3, out);
    render_kernel<<<512, 256>>>(rays_o, rays_d, variance, out);
}